// round 1
// baseline (speedup 1.0000x reference)
#include <cuda_runtime.h>
#include <cstdint>

// Problem constants
#define BATCH   16
#define TLEN    4096
#define DIMX    256
#define HID     128
#define G3      384          // 3*HID gate width
#define NLAYER  3
#define MROWS   (BATCH * TLEN)   // 65536

// Scratch (device globals — no runtime allocation allowed)
// xg[dir][b*T + t][384]  (input-side gate pre-activations for current layer)
__device__ float g_xg[(size_t)2 * MROWS * G3];        // ~201 MB
// layer activation ping buffer [b][t][256]
__device__ float g_y[(size_t)MROWS * DIMX];           // 64 MB

// ---------------- f32x2 packed helpers (Blackwell sm_103a) ----------------
__device__ __forceinline__ unsigned long long pk2(float lo, float hi) {
    unsigned long long r;
    asm("mov.b64 %0, {%1, %2};" : "=l"(r) : "f"(lo), "f"(hi));
    return r;
}
__device__ __forceinline__ void up2(unsigned long long v, float& lo, float& hi) {
    asm("mov.b64 {%0, %1}, %2;" : "=f"(lo), "=f"(hi) : "l"(v));
}
__device__ __forceinline__ unsigned long long fma2(unsigned long long a,
                                                   unsigned long long b,
                                                   unsigned long long c) {
    unsigned long long d;
    asm("fma.rn.f32x2 %0, %1, %2, %3;" : "=l"(d) : "l"(a), "l"(b), "l"(c));
    return d;
}
__device__ __forceinline__ unsigned long long fadd2(unsigned long long a,
                                                    unsigned long long b) {
    unsigned long long d;
    asm("add.rn.f32x2 %0, %1, %2;" : "=l"(d) : "l"(a), "l"(b));
    return d;
}

__device__ __forceinline__ float sigmf(float x) {
    return __fdividef(1.0f, 1.0f + __expf(-x));
}
__device__ __forceinline__ float tanhfast(float x) {
    // stable: tanh(x) = sign(x) * (1 - e^{-2|x|}) / (1 + e^{-2|x|})
    float t = __expf(-2.0f * fabsf(x));
    float r = __fdividef(1.0f - t, 1.0f + t);
    return copysignf(r, x);
}

// ---------------------------------------------------------------------------
// Input-side GEMM: xg[dir] = A(65536x256) @ Wi[l][dir](256x384)
// Tile 128x64, BK=16, 256 threads, 8x4 micro-tile, M-paired f32x2.
// ---------------------------------------------------------------------------
__global__ void __launch_bounds__(256) gemm_xg(const float* __restrict__ A,
                                               const float* __restrict__ Wl) {
    const int dir = blockIdx.z;
    const float* Bm = Wl + (size_t)dir * DIMX * G3;
    float* C = g_xg + (size_t)dir * MROWS * G3;

    const int m0 = blockIdx.x * 128;
    const int n0 = blockIdx.y * 64;

    __shared__ __align__(16) float As[16][132];  // [k][m], padded (stride 132 keeps 16B align)
    __shared__ __align__(16) float Bs[16][64];   // [k][n]

    const int tid = threadIdx.x;
    const int ty = tid >> 4;         // 0..15 -> row group (8 rows)
    const int tx = tid & 15;         // 0..15 -> col group (4 cols)
    const int arow = tid >> 2;       // 0..63
    const int ak   = (tid & 3) << 2; // 0,4,8,12
    const int bk   = tid >> 4;       // 0..15
    const int bn   = (tid & 15) << 2;

    unsigned long long c2[4][4];
#pragma unroll
    for (int i = 0; i < 4; i++)
#pragma unroll
        for (int j = 0; j < 4; j++) c2[i][j] = 0ULL;

    for (int k0 = 0; k0 < DIMX; k0 += 16) {
        float4 a0 = *(const float4*)&A[(size_t)(m0 + arow) * DIMX + k0 + ak];
        float4 a1 = *(const float4*)&A[(size_t)(m0 + arow + 64) * DIMX + k0 + ak];
        float4 bv = *(const float4*)&Bm[(size_t)(k0 + bk) * G3 + n0 + bn];
        __syncthreads();
        As[ak + 0][arow] = a0.x; As[ak + 1][arow] = a0.y;
        As[ak + 2][arow] = a0.z; As[ak + 3][arow] = a0.w;
        As[ak + 0][arow + 64] = a1.x; As[ak + 1][arow + 64] = a1.y;
        As[ak + 2][arow + 64] = a1.z; As[ak + 3][arow + 64] = a1.w;
        *(float4*)&Bs[bk][bn] = bv;
        __syncthreads();

#pragma unroll
        for (int k = 0; k < 16; k++) {
            ulonglong2 av0 = *(const ulonglong2*)&As[k][ty * 8];
            ulonglong2 av1 = *(const ulonglong2*)&As[k][ty * 8 + 4];
            float4 b4 = *(const float4*)&Bs[k][tx * 4];
            unsigned long long bb0 = pk2(b4.x, b4.x);
            unsigned long long bb1 = pk2(b4.y, b4.y);
            unsigned long long bb2 = pk2(b4.z, b4.z);
            unsigned long long bb3 = pk2(b4.w, b4.w);
            c2[0][0] = fma2(av0.x, bb0, c2[0][0]);
            c2[0][1] = fma2(av0.x, bb1, c2[0][1]);
            c2[0][2] = fma2(av0.x, bb2, c2[0][2]);
            c2[0][3] = fma2(av0.x, bb3, c2[0][3]);
            c2[1][0] = fma2(av0.y, bb0, c2[1][0]);
            c2[1][1] = fma2(av0.y, bb1, c2[1][1]);
            c2[1][2] = fma2(av0.y, bb2, c2[1][2]);
            c2[1][3] = fma2(av0.y, bb3, c2[1][3]);
            c2[2][0] = fma2(av1.x, bb0, c2[2][0]);
            c2[2][1] = fma2(av1.x, bb1, c2[2][1]);
            c2[2][2] = fma2(av1.x, bb2, c2[2][2]);
            c2[2][3] = fma2(av1.x, bb3, c2[2][3]);
            c2[3][0] = fma2(av1.y, bb0, c2[3][0]);
            c2[3][1] = fma2(av1.y, bb1, c2[3][1]);
            c2[3][2] = fma2(av1.y, bb2, c2[3][2]);
            c2[3][3] = fma2(av1.y, bb3, c2[3][3]);
        }
    }

#pragma unroll
    for (int rp = 0; rp < 4; rp++) {
        float l0, h0, l1, h1, l2, h2, l3, h3;
        up2(c2[rp][0], l0, h0);
        up2(c2[rp][1], l1, h1);
        up2(c2[rp][2], l2, h2);
        up2(c2[rp][3], l3, h3);
        const int row = m0 + ty * 8 + rp * 2;
        float4 v0 = make_float4(l0, l1, l2, l3);
        float4 v1 = make_float4(h0, h1, h2, h3);
        *(float4*)&C[(size_t)row * G3 + n0 + tx * 4] = v0;
        *(float4*)&C[(size_t)(row + 1) * G3 + n0 + tx * 4] = v1;
    }
}

// ---------------------------------------------------------------------------
// Sequential GRU recurrence for one layer (both directions, all batches).
// grid = 32 blocks: block -> (dir, batch). 384 threads: thread j owns gate
// column j; its 128 Wh weights live in registers as 64 f32x2 pairs.
// h (128 floats) lives in smem, read as ulonglong2 broadcasts.
// ---------------------------------------------------------------------------
__global__ void __launch_bounds__(384, 1)
gru_recur(const float* __restrict__ Whl,   // [2][128][384] for this layer
          const float* __restrict__ bhl,   // [2][384]
          float* __restrict__ yout) {      // [b][t][256]
    const int blk = blockIdx.x;
    const int d = blk >> 4;       // direction
    const int b = blk & 15;       // batch
    const int j = threadIdx.x;    // 0..383 gate column
    const int gate = j >> 7;      // 0=r, 1=z, 2=n
    const int jj = j & 127;

    const float* Wd = Whl + (size_t)d * HID * G3;
    const float* xgb = g_xg + ((size_t)d * MROWS + (size_t)b * TLEN) * G3;
    const float bias = bhl[d * G3 + j];

    // Load this thread's weight column into registers as k-pairs
    unsigned long long w2[64];
#pragma unroll
    for (int i = 0; i < 64; i++)
        w2[i] = pk2(Wd[(size_t)(2 * i) * G3 + j], Wd[(size_t)(2 * i + 1) * G3 + j]);

    __shared__ __align__(16) float h_s[HID];
    __shared__ float r_s[HID];
    __shared__ float z_s[HID];
    if (j < HID) h_s[j] = 0.0f;
    __syncthreads();

    int t = d ? (TLEN - 1) : 0;
    const int dt = d ? -1 : 1;
    float xv = xgb[(size_t)t * G3 + j];
    float* ybase = yout + (size_t)b * TLEN * DIMX + d * HID + jj;

    for (int s = 0; s < TLEN; s++) {
        // prefetch next timestep's input-gate value
        float xnext = 0.0f;
        if (s < TLEN - 1) xnext = xgb[(size_t)(t + dt) * G3 + j];

        // matvec: hdot = sum_k h[k] * Wh[k][j]   (f32x2 packed, 4 acc chains)
        unsigned long long a0 = 0ULL, a1 = 0ULL, a2 = 0ULL, a3 = 0ULL;
        const ulonglong2* h2 = (const ulonglong2*)h_s;
#pragma unroll
        for (int i = 0; i < 32; i += 2) {
            ulonglong2 hv0 = h2[i];
            ulonglong2 hv1 = h2[i + 1];
            a0 = fma2(hv0.x, w2[2 * i],     a0);
            a1 = fma2(hv0.y, w2[2 * i + 1], a1);
            a2 = fma2(hv1.x, w2[2 * i + 2], a2);
            a3 = fma2(hv1.y, w2[2 * i + 3], a3);
        }
        a0 = fadd2(a0, a2);
        a1 = fadd2(a1, a3);
        a0 = fadd2(a0, a1);
        float lo, hi;
        up2(a0, lo, hi);
        const float hdot = lo + hi;

        if (gate == 0)      r_s[jj] = sigmf(xv + hdot + bias);
        else if (gate == 1) z_s[jj] = sigmf(xv + hdot + bias);
        __syncthreads();

        if (gate == 2) {
            float n = tanhfast(xv + r_s[jj] * (hdot + bias));
            float z = z_s[jj];
            float hn = (1.0f - z) * n + z * h_s[jj];
            h_s[jj] = hn;                 // safe: all reads done before barrier
            ybase[(size_t)t * DIMX] = hn; // time-aligned output
        }
        __syncthreads();

        xv = xnext;
        t += dt;
    }
}

// ---------------------------------------------------------------------------
extern "C" void kernel_launch(void* const* d_in, const int* in_sizes, int n_in,
                              void* d_out, int out_size) {
    const float* x  = (const float*)d_in[0];   // [16,4096,256]
    const float* Wi = (const float*)d_in[1];   // [3,2,256,384]
    const float* Wh = (const float*)d_in[2];   // [3,2,128,384]
    const float* bh = (const float*)d_in[3];   // [3,2,384]
    float* out = (float*)d_out;                // [16,4096,256]

    float* yscratch = nullptr;
    cudaGetSymbolAddress((void**)&yscratch, g_y);

    dim3 ggrid(MROWS / 128, G3 / 64, 2);

    for (int l = 0; l < NLAYER; l++) {
        const float* yin = (l == 0) ? x : yscratch;
        gemm_xg<<<ggrid, 256>>>(yin, Wi + (size_t)l * 2 * DIMX * G3);

        float* yo = (l == NLAYER - 1) ? out : yscratch;
        gru_recur<<<32, 384>>>(Wh + (size_t)l * 2 * HID * G3,
                               bh + (size_t)l * 2 * G3, yo);
    }
}

// round 2
// speedup vs baseline: 1.0743x; 1.0743x over previous
#include <cuda_runtime.h>
#include <cstdint>

// Problem constants
#define BATCH   16
#define TLEN    4096
#define DIMX    256
#define HID     128
#define G3      384
#define NLAYER  3
#define MROWS   (BATCH * TLEN)      // 65536

// Persistent-kernel structure
#define NBLK    148
#define RECB    32
#define GEMB    (NBLK - RECB)       // 116

// GEMM tiling
#define BM      128
#define BN      96
#define BK      16
#define NT_PER  (G3 / BN)           // 4 N-tiles per row-chunk
#define NCHUNK  (TLEN / BM)         // 32 time-chunks per sequence
#define TILES_PER_LAYER (2 * BATCH * NCHUNK * NT_PER)   // 4096

// -------- scratch (device globals; no runtime allocation allowed) ----------
__device__ float g_xgA[(size_t)2 * MROWS * G3];   // xg for layers 0,2
__device__ float g_xgB[(size_t)2 * MROWS * G3];   // xg for layer 1
__device__ float g_yA[(size_t)MROWS * DIMX];      // layer-0 output
__device__ float g_yB[(size_t)MROWS * DIMX];      // layer-1 output
__device__ unsigned g_fwdsteps[NLAYER][BATCH];
__device__ unsigned g_bwdsteps[NLAYER][BATCH];
__device__ unsigned g_xgready[NLAYER][2][BATCH][NCHUNK];

// ---------------- f32x2 packed helpers (Blackwell sm_103a) -----------------
__device__ __forceinline__ unsigned long long pk2(float lo, float hi) {
    unsigned long long r;
    asm("mov.b64 %0, {%1, %2};" : "=l"(r) : "f"(lo), "f"(hi));
    return r;
}
__device__ __forceinline__ void up2(unsigned long long v, float& lo, float& hi) {
    asm("mov.b64 {%0, %1}, %2;" : "=f"(lo), "=f"(hi) : "l"(v));
}
__device__ __forceinline__ unsigned long long fma2(unsigned long long a,
                                                   unsigned long long b,
                                                   unsigned long long c) {
    unsigned long long d;
    asm("fma.rn.f32x2 %0, %1, %2, %3;" : "=l"(d) : "l"(a), "l"(b), "l"(c));
    return d;
}
__device__ __forceinline__ unsigned long long fadd2(unsigned long long a,
                                                    unsigned long long b) {
    unsigned long long d;
    asm("add.rn.f32x2 %0, %1, %2;" : "=l"(d) : "l"(a), "l"(b));
    return d;
}
__device__ __forceinline__ float sigmf(float x) {
    return __fdividef(1.0f, 1.0f + __expf(-x));
}
__device__ __forceinline__ float tanhfast(float x) {
    float t = __expf(-2.0f * fabsf(x));
    float r = __fdividef(1.0f - t, 1.0f + t);
    return copysignf(r, x);
}
__device__ __forceinline__ unsigned ldv(const unsigned* p) {
    return *(volatile const unsigned*)p;
}

// -------------------------- flag reset kernel ------------------------------
__global__ void reset_flags() {
    int i = blockIdx.x * blockDim.x + threadIdx.x;
    unsigned* r = &g_xgready[0][0][0][0];
    const int nr = NLAYER * 2 * BATCH * NCHUNK;   // 3072
    if (i < nr) r[i] = 0;
    if (i < NLAYER * BATCH) {
        (&g_fwdsteps[0][0])[i] = 0;
        (&g_bwdsteps[0][0])[i] = 0;
    }
}

// ------------------------- persistent fused kernel -------------------------
__global__ void __launch_bounds__(384, 1)
fused_birnn(const float* __restrict__ xin,
            const float* __restrict__ Wi,   // [3][2][256][384]
            const float* __restrict__ Wh,   // [3][2][128][384]
            const float* __restrict__ bh,   // [3][2][384]
            float* __restrict__ out) {
    // static shared: GEMM double buffers + recurrence state (43 KB total)
    __shared__ __align__(16) float sh_As[2][BK][BM + 4];
    __shared__ __align__(16) unsigned long long sh_Bs[2][BK][BN];
    __shared__ __align__(16) float sh_h[HID];
    __shared__ float sh_r[HID];
    __shared__ float sh_z[HID];

    const int tid = threadIdx.x;

    if (blockIdx.x < RECB) {
        // ================= RECURRENCE ROLE (blocks 0..31) ==================
        const int d = blockIdx.x >> 4;
        const int b = blockIdx.x & 15;
        const int j = tid;
        const int gate = j >> 7;
        const int jj = j & 127;
        const int dt = d ? -1 : 1;

        for (int l = 0; l < NLAYER; l++) {
            const float* Wd = Wh + (size_t)(l * 2 + d) * HID * G3;
            const float bias = bh[(l * 2 + d) * G3 + j];
            const float* xgbuf = (l == 1) ? g_xgB : g_xgA;
            const float* xgb = xgbuf + ((size_t)d * MROWS + (size_t)b * TLEN) * G3;
            float* yo = (l == 0) ? g_yA : (l == 1) ? g_yB : out;
            const unsigned* rdy = &g_xgready[l][d][b][0];

            unsigned long long w2[64];
#pragma unroll
            for (int i = 0; i < 64; i++)
                w2[i] = pk2(Wd[(2 * i) * G3 + j], Wd[(2 * i + 1) * G3 + j]);

            if (j < HID) sh_h[j] = 0.0f;

            // wait for first consumed chunk of this layer's xg
            if (j == 0) {
                int c0 = d ? (NCHUNK - 1) : 0;
                while (ldv(&rdy[c0]) < NT_PER) __nanosleep(64);
            }
            __syncthreads();
            __threadfence();

            int t = d ? (TLEN - 1) : 0;
            float x0 = xgb[t * G3 + j];
            float x1 = xgb[(t + dt) * G3 + j];
            float* ybase = yo + (size_t)b * TLEN * DIMX + d * HID + jj;

            for (int s = 0; s < TLEN; s++) {
                float x2 = 0.0f;
                if (s + 2 < TLEN) {
                    if (((s + 2) & 127) == 0) {
                        // crossing into a new xg chunk two steps ahead
                        int cw = (s + 2) >> 7;
                        int ci = d ? (NCHUNK - 1 - cw) : cw;
                        if (j == 0) {
                            while (ldv(&rdy[ci]) < NT_PER) __nanosleep(64);
                        }
                        __syncthreads();
                        __threadfence();
                    }
                    x2 = xgb[(t + 2 * dt) * G3 + j];
                }

                // matvec: hdot = sum_k h[k] * Wh[k][j]
                unsigned long long a0 = 0ULL, a1 = 0ULL, a2 = 0ULL, a3 = 0ULL;
                const ulonglong2* h2 = (const ulonglong2*)sh_h;
#pragma unroll
                for (int i = 0; i < 32; i += 2) {
                    ulonglong2 hv0 = h2[i];
                    ulonglong2 hv1 = h2[i + 1];
                    a0 = fma2(hv0.x, w2[2 * i],     a0);
                    a1 = fma2(hv0.y, w2[2 * i + 1], a1);
                    a2 = fma2(hv1.x, w2[2 * i + 2], a2);
                    a3 = fma2(hv1.y, w2[2 * i + 3], a3);
                }
                a0 = fadd2(a0, a2);
                a1 = fadd2(a1, a3);
                a0 = fadd2(a0, a1);
                float lo, hi;
                up2(a0, lo, hi);
                const float hdot = lo + hi;

                if (gate == 0)      sh_r[jj] = sigmf(x0 + hdot + bias);
                else if (gate == 1) sh_z[jj] = sigmf(x0 + hdot + bias);
                __syncthreads();

                if (gate == 2) {
                    float n = tanhfast(x0 + sh_r[jj] * (hdot + bias));
                    float z = sh_z[jj];
                    float hp = sh_h[jj];
                    float hn = fmaf(z, hp - n, n);
                    sh_h[jj] = hn;
                    ybase[(size_t)t * DIMX] = hn;
                }
                __syncthreads();

                if (((s + 1) & 127) == 0 && j == 0) {
                    __threadfence();  // make y writes (+ all prior) gpu-visible
                    volatile unsigned* pp =
                        d ? &g_bwdsteps[l][b] : &g_fwdsteps[l][b];
                    *pp = (unsigned)(s + 1);
                }

                x0 = x1;
                x1 = x2;
                t += dt;
            }
        }
    } else {
        // =================== GEMM ROLE (blocks 32..147) ====================
        const int gid = blockIdx.x - RECB;
        const int ty8 = (tid / 24) * 8;     // row group within 128
        const int tx4 = (tid % 24) * 4;     // col group within 96
        const int arow = tid >> 2;          // A-load: rows 0..95
        const int ak = (tid & 3) << 2;
        const int brow = tid / 24;          // B-load: k-row 0..15
        const int bc = (tid % 24) * 4;

        for (int l = 0; l < NLAYER; l++) {
            const float* Asrc = (l == 0) ? xin : (l == 1) ? g_yA : g_yB;
            float* xgdst = (l == 1) ? g_xgB : g_xgA;
            const float* Wl = Wi + (size_t)l * 2 * DIMX * G3;

            for (int rank = gid; rank < TILES_PER_LAYER; rank += GEMB) {
                const int o = rank >> 7;
                const int rem = rank & 127;
                const int dir = rem >> 6;
                const int b = (rem >> 2) & 15;
                const int nt = rem & 3;
                int ci;
                if (l == 0)  // ends-first (matches recurrence consumption)
                    ci = (o & 1) ? (NCHUNK - 1 - (o >> 1)) : (o >> 1);
                else         // middle-out (matches producer readiness)
                    ci = (o & 1) ? (NCHUNK / 2 + (o >> 1))
                                 : (NCHUNK / 2 - 1 - (o >> 1));

                if (l > 0) {
                    if (tid == 0) {
                        unsigned needf = (unsigned)((ci + 1) * BM);
                        unsigned needb = (unsigned)(TLEN - ci * BM);
                        while (ldv(&g_fwdsteps[l - 1][b]) < needf) __nanosleep(128);
                        while (ldv(&g_bwdsteps[l - 1][b]) < needb) __nanosleep(128);
                    }
                    __syncthreads();
                    __threadfence();
                }

                const float* At = Asrc + ((size_t)b * TLEN + (size_t)ci * BM) * DIMX;
                const float* Bt = Wl + (size_t)dir * DIMX * G3 + nt * BN;
                float* Ct = xgdst + (size_t)dir * MROWS * G3 +
                            ((size_t)b * TLEN + (size_t)ci * BM) * G3 + nt * BN;

                unsigned long long acc[4][4];
#pragma unroll
                for (int i = 0; i < 4; i++)
#pragma unroll
                    for (int q = 0; q < 4; q++) acc[i][q] = 0ULL;

                // prologue: load chunk 0
                float4 a0r = *(const float4*)&At[(size_t)arow * DIMX + ak];
                float4 a1r = make_float4(0.f, 0.f, 0.f, 0.f);
                if (tid < 128)
                    a1r = *(const float4*)&At[(size_t)(arow + 96) * DIMX + ak];
                float4 b0r = *(const float4*)&Bt[(size_t)brow * G3 + bc];

                sh_As[0][ak + 0][arow] = a0r.x;
                sh_As[0][ak + 1][arow] = a0r.y;
                sh_As[0][ak + 2][arow] = a0r.z;
                sh_As[0][ak + 3][arow] = a0r.w;
                if (tid < 128) {
                    sh_As[0][ak + 0][arow + 96] = a1r.x;
                    sh_As[0][ak + 1][arow + 96] = a1r.y;
                    sh_As[0][ak + 2][arow + 96] = a1r.z;
                    sh_As[0][ak + 3][arow + 96] = a1r.w;
                }
                {
                    ulonglong2 bp0, bp1;
                    bp0.x = pk2(b0r.x, b0r.x); bp0.y = pk2(b0r.y, b0r.y);
                    bp1.x = pk2(b0r.z, b0r.z); bp1.y = pk2(b0r.w, b0r.w);
                    *(ulonglong2*)&sh_Bs[0][brow][bc] = bp0;
                    *(ulonglong2*)&sh_Bs[0][brow][bc + 2] = bp1;
                }
                __syncthreads();

                for (int c = 0; c < DIMX / BK; c++) {
                    const int cur = c & 1;
                    if (c < DIMX / BK - 1) {
                        const int k0 = (c + 1) * BK;
                        a0r = *(const float4*)&At[(size_t)arow * DIMX + k0 + ak];
                        if (tid < 128)
                            a1r = *(const float4*)&At[(size_t)(arow + 96) * DIMX + k0 + ak];
                        b0r = *(const float4*)&Bt[(size_t)(k0 + brow) * G3 + bc];
                    }
#pragma unroll
                    for (int k = 0; k < BK; k++) {
                        const float* Ak = &sh_As[cur][k][ty8];
                        ulonglong2 av0 = *(const ulonglong2*)(Ak);
                        ulonglong2 av1 = *(const ulonglong2*)(Ak + 4);
                        const unsigned long long* Bk = &sh_Bs[cur][k][tx4];
                        ulonglong2 bv0 = *(const ulonglong2*)(Bk);
                        ulonglong2 bv1 = *(const ulonglong2*)(Bk + 2);
                        acc[0][0] = fma2(av0.x, bv0.x, acc[0][0]);
                        acc[0][1] = fma2(av0.x, bv0.y, acc[0][1]);
                        acc[0][2] = fma2(av0.x, bv1.x, acc[0][2]);
                        acc[0][3] = fma2(av0.x, bv1.y, acc[0][3]);
                        acc[1][0] = fma2(av0.y, bv0.x, acc[1][0]);
                        acc[1][1] = fma2(av0.y, bv0.y, acc[1][1]);
                        acc[1][2] = fma2(av0.y, bv1.x, acc[1][2]);
                        acc[1][3] = fma2(av0.y, bv1.y, acc[1][3]);
                        acc[2][0] = fma2(av1.x, bv0.x, acc[2][0]);
                        acc[2][1] = fma2(av1.x, bv0.y, acc[2][1]);
                        acc[2][2] = fma2(av1.x, bv1.x, acc[2][2]);
                        acc[2][3] = fma2(av1.x, bv1.y, acc[2][3]);
                        acc[3][0] = fma2(av1.y, bv0.x, acc[3][0]);
                        acc[3][1] = fma2(av1.y, bv0.y, acc[3][1]);
                        acc[3][2] = fma2(av1.y, bv1.x, acc[3][2]);
                        acc[3][3] = fma2(av1.y, bv1.y, acc[3][3]);
                    }
                    if (c < DIMX / BK - 1) {
                        const int nxt = cur ^ 1;
                        sh_As[nxt][ak + 0][arow] = a0r.x;
                        sh_As[nxt][ak + 1][arow] = a0r.y;
                        sh_As[nxt][ak + 2][arow] = a0r.z;
                        sh_As[nxt][ak + 3][arow] = a0r.w;
                        if (tid < 128) {
                            sh_As[nxt][ak + 0][arow + 96] = a1r.x;
                            sh_As[nxt][ak + 1][arow + 96] = a1r.y;
                            sh_As[nxt][ak + 2][arow + 96] = a1r.z;
                            sh_As[nxt][ak + 3][arow + 96] = a1r.w;
                        }
                        ulonglong2 bp0, bp1;
                        bp0.x = pk2(b0r.x, b0r.x); bp0.y = pk2(b0r.y, b0r.y);
                        bp1.x = pk2(b0r.z, b0r.z); bp1.y = pk2(b0r.w, b0r.w);
                        *(ulonglong2*)&sh_Bs[nxt][brow][bc] = bp0;
                        *(ulonglong2*)&sh_Bs[nxt][brow][bc + 2] = bp1;
                        __syncthreads();
                    }
                }

                // epilogue: unpack and store
#pragma unroll
                for (int mp = 0; mp < 4; mp++) {
                    float l0, h0, l1, h1, l2, h2, l3, h3;
                    up2(acc[mp][0], l0, h0);
                    up2(acc[mp][1], l1, h1);
                    up2(acc[mp][2], l2, h2);
                    up2(acc[mp][3], l3, h3);
                    const int row = ty8 + 2 * mp;
                    *(float4*)&Ct[(size_t)row * G3 + tx4] =
                        make_float4(l0, l1, l2, l3);
                    *(float4*)&Ct[(size_t)(row + 1) * G3 + tx4] =
                        make_float4(h0, h1, h2, h3);
                }
                __syncthreads();
                if (tid == 0) {
                    __threadfence();
                    atomicAdd(&g_xgready[l][dir][b][ci], 1u);
                }
                __syncthreads();
            }
        }
    }
}

// ---------------------------------------------------------------------------
extern "C" void kernel_launch(void* const* d_in, const int* in_sizes, int n_in,
                              void* d_out, int out_size) {
    const float* x  = (const float*)d_in[0];   // [16,4096,256]
    const float* Wi = (const float*)d_in[1];   // [3,2,256,384]
    const float* Wh = (const float*)d_in[2];   // [3,2,128,384]
    const float* bh = (const float*)d_in[3];   // [3,2,384]
    float* out = (float*)d_out;                // [16,4096,256]

    reset_flags<<<(NLAYER * 2 * BATCH * NCHUNK + 255) / 256, 256>>>();
    fused_birnn<<<NBLK, 384>>>(x, Wi, Wh, bh, out);
}

// round 5
// speedup vs baseline: 1.1354x; 1.0569x over previous
#include <cuda_runtime.h>
#include <cstdint>

// Problem constants
#define BATCH   16
#define TLEN    4096
#define DIMX    256
#define HID     128
#define G3      384
#define NLAYER  3
#define MROWS   (BATCH * TLEN)      // 65536

// Persistent-kernel structure
#define NBLK    148
#define RECB    32
#define GEMB    (NBLK - RECB)       // 116

// GEMM tiling
#define BM      128
#define BN      96
#define BK      16
#define NT_PER  (G3 / BN)           // 4
#define NCHUNK  (TLEN / BM)         // 32
#define TILES_PER_LAYER (2 * BATCH * NCHUNK * NT_PER)   // 4096

// -------- scratch (device globals; no runtime allocation allowed) ----------
__device__ float g_xgA[(size_t)2 * MROWS * G3];
__device__ float g_xgB[(size_t)2 * MROWS * G3];
__device__ float g_yA[(size_t)MROWS * DIMX];
__device__ float g_yB[(size_t)MROWS * DIMX];
__device__ unsigned g_fwdsteps[NLAYER][BATCH];
__device__ unsigned g_bwdsteps[NLAYER][BATCH];
__device__ unsigned g_xgready[NLAYER][2][BATCH][NCHUNK];

// ---------------- f32x2 packed helpers (Blackwell sm_103a) -----------------
__device__ __forceinline__ unsigned long long pk2(float lo, float hi) {
    unsigned long long r;
    asm("mov.b64 %0, {%1, %2};" : "=l"(r) : "f"(lo), "f"(hi));
    return r;
}
__device__ __forceinline__ void up2(unsigned long long v, float& lo, float& hi) {
    asm("mov.b64 {%0, %1}, %2;" : "=f"(lo), "=f"(hi) : "l"(v));
}
__device__ __forceinline__ unsigned long long fma2(unsigned long long a,
                                                   unsigned long long b,
                                                   unsigned long long c) {
    unsigned long long d;
    asm("fma.rn.f32x2 %0, %1, %2, %3;" : "=l"(d) : "l"(a), "l"(b), "l"(c));
    return d;
}
__device__ __forceinline__ unsigned long long fadd2(unsigned long long a,
                                                    unsigned long long b) {
    unsigned long long d;
    asm("add.rn.f32x2 %0, %1, %2;" : "=l"(d) : "l"(a), "l"(b));
    return d;
}
__device__ __forceinline__ float sigmf(float x) {
    return __fdividef(1.0f, 1.0f + __expf(-x));
}
__device__ __forceinline__ float tanhfast(float x) {
    float t = __expf(-2.0f * fabsf(x));
    float r = __fdividef(1.0f - t, 1.0f + t);
    return copysignf(r, x);
}
__device__ __forceinline__ unsigned ldv(const unsigned* p) {
    return *(volatile const unsigned*)p;
}

// -------------------------- flag reset kernel ------------------------------
__global__ void reset_flags() {
    int i = blockIdx.x * blockDim.x + threadIdx.x;
    unsigned* r = &g_xgready[0][0][0][0];
    const int nr = NLAYER * 2 * BATCH * NCHUNK;
    if (i < nr) r[i] = 0;
    if (i < NLAYER * BATCH) {
        (&g_fwdsteps[0][0])[i] = 0;
        (&g_bwdsteps[0][0])[i] = 0;
    }
}

// --------------------------- one GRU timestep ------------------------------
__device__ __forceinline__ void gru_step(
    const float*& xp, float& x0, float& x1, float*& yp,
    long sstride, long ystride, long pf_off,
    const unsigned long long* w2, float bias,
    int gate, int jj, float* sh_h, float* sh_g)
{
    float x2 = __ldg(xp + pf_off);

    // matvec over ALL 128 h values: h2[0..31], w2[0..63]
    unsigned long long a0 = 0ULL, a1 = 0ULL;
    const ulonglong2* h2 = (const ulonglong2*)sh_h;
#pragma unroll
    for (int i = 0; i < 32; i++) {
        ulonglong2 hv = h2[i];
        a0 = fma2(hv.x, w2[2 * i],     a0);
        a1 = fma2(hv.y, w2[2 * i + 1], a1);
    }
    a0 = fadd2(a0, a1);
    float lo, hi;
    up2(a0, lo, hi);
    const float q = lo + hi + bias;   // hdot + bias

    if (gate < 2) sh_g[gate * HID + jj] = sigmf(x0 + q);
    __syncthreads();

    if (gate == 2) {
        float r = sh_g[jj];
        float n = tanhfast(fmaf(r, q, x0));
        float z = sh_g[HID + jj];
        float hp = sh_h[jj];
        float hn = fmaf(z, hp - n, n);
        sh_h[jj] = hn;
        *yp = hn;
    }
    __syncthreads();

    x0 = x1;
    x1 = x2;
    xp += sstride;
    yp += ystride;
}

// ------------------------- persistent fused kernel -------------------------
__global__ void __launch_bounds__(384, 1)
fused_birnn(const float* __restrict__ xin,
            const float* __restrict__ Wi,   // [3][2][256][384]
            const float* __restrict__ Wh,   // [3][2][128][384]
            const float* __restrict__ bh,   // [3][2][384]
            float* __restrict__ out) {
    __shared__ __align__(16) float sh_As[2][BK][BM + 4];
    __shared__ __align__(16) unsigned long long sh_Bs[2][BK][BN];
    __shared__ __align__(16) float sh_h[HID];
    __shared__ __align__(16) float sh_g[2 * HID];   // [r | z]

    const int tid = threadIdx.x;

    if (blockIdx.x < RECB) {
        // ================= RECURRENCE ROLE (blocks 0..31) ==================
        const int d = blockIdx.x >> 4;
        const int b = blockIdx.x & 15;
        const int j = tid;
        const int gate = j >> 7;
        const int jj = j & 127;
        const int dt = d ? -1 : 1;
        const long sstride = (long)dt * G3;
        const long ystride = (long)dt * DIMX;

        for (int l = 0; l < NLAYER; l++) {
            const float* Wd = Wh + (size_t)(l * 2 + d) * HID * G3;
            const float bias = bh[(l * 2 + d) * G3 + j];
            const float* xgbuf = (l == 1) ? g_xgB : g_xgA;
            const float* xgb = xgbuf + ((size_t)d * MROWS + (size_t)b * TLEN) * G3;
            float* yo = (l == 0) ? g_yA : (l == 1) ? g_yB : out;
            const unsigned* rdy = &g_xgready[l][d][b][0];

            unsigned long long w2[64];
#pragma unroll
            for (int i = 0; i < 64; i++)
                w2[i] = pk2(Wd[(2 * i) * G3 + j], Wd[(2 * i + 1) * G3 + j]);

            if (j < HID) sh_h[j] = 0.0f;

            // wait for first consumed chunk
            {
                const int c0 = d ? (NCHUNK - 1) : 0;
                if (j == 0) {
                    while (ldv(&rdy[c0]) < NT_PER) __nanosleep(64);
                }
            }
            __syncthreads();
            __threadfence();

            const int t0 = d ? (TLEN - 1) : 0;
            const float* xp = xgb + (size_t)t0 * G3 + j;
            float x0 = __ldg(xp);
            float x1 = __ldg(xp + sstride);
            float* yp = yo + (size_t)b * TLEN * DIMX + (size_t)t0 * DIMX
                        + d * HID + jj;
            unsigned done = 0;

            for (int c = 0; c < NCHUNK; c++) {
                // 126 branch-free steps (prefetch stays inside chunk c)
                for (int u = 0; u < 126; u++) {
                    gru_step(xp, x0, x1, yp, sstride, ystride, 2 * sstride,
                             w2, bias, gate, jj, sh_h, sh_g);
                }
                if (c < NCHUNK - 1) {
                    // next chunk must be ready before prefetching into it
                    const int cn = d ? (NCHUNK - 2 - c) : (c + 1);
                    if (j == 0) {
                        while (ldv(&rdy[cn]) < NT_PER) __nanosleep(64);
                    }
                    __syncthreads();
                    __threadfence();
                    gru_step(xp, x0, x1, yp, sstride, ystride, 2 * sstride,
                             w2, bias, gate, jj, sh_h, sh_g);
                    gru_step(xp, x0, x1, yp, sstride, ystride, 2 * sstride,
                             w2, bias, gate, jj, sh_h, sh_g);
                } else {
                    // last chunk: clamp prefetch (reload current, unused)
                    gru_step(xp, x0, x1, yp, sstride, ystride, 0,
                             w2, bias, gate, jj, sh_h, sh_g);
                    gru_step(xp, x0, x1, yp, sstride, ystride, 0,
                             w2, bias, gate, jj, sh_h, sh_g);
                }
                done += BM;
                if (j == 0) {
                    __threadfence();
                    *(volatile unsigned*)(d ? &g_bwdsteps[l][b]
                                            : &g_fwdsteps[l][b]) = done;
                }
            }
        }
    } else {
        // =================== GEMM ROLE (blocks 32..147) ====================
        const int gid = blockIdx.x - RECB;
        const int ty8 = (tid / 24) * 8;
        const int tx4 = (tid % 24) * 4;
        const int arow = tid >> 2;
        const int ak = (tid & 3) << 2;
        const int brow = tid / 24;
        const int bc = (tid % 24) * 4;

        for (int l = 0; l < NLAYER; l++) {
            const float* Asrc = (l == 0) ? xin : (l == 1) ? g_yA : g_yB;
            float* xgdst = (l == 1) ? g_xgB : g_xgA;
            const float* Wl = Wi + (size_t)l * 2 * DIMX * G3;

            for (int rank = gid; rank < TILES_PER_LAYER; rank += GEMB) {
                const int o = rank >> 7;
                const int rem = rank & 127;
                const int dir = rem >> 6;
                const int b = (rem >> 2) & 15;
                const int nt = rem & 3;
                int ci;
                if (l == 0)
                    ci = (o & 1) ? (NCHUNK - 1 - (o >> 1)) : (o >> 1);
                else
                    ci = (o & 1) ? (NCHUNK / 2 + (o >> 1))
                                 : (NCHUNK / 2 - 1 - (o >> 1));

                if (l > 0) {
                    if (tid == 0) {
                        unsigned needf = (unsigned)((ci + 1) * BM);
                        unsigned needb = (unsigned)(TLEN - ci * BM);
                        while (ldv(&g_fwdsteps[l - 1][b]) < needf) __nanosleep(128);
                        while (ldv(&g_bwdsteps[l - 1][b]) < needb) __nanosleep(128);
                    }
                    __syncthreads();
                    __threadfence();
                }

                const float* At = Asrc + ((size_t)b * TLEN + (size_t)ci * BM) * DIMX;
                const float* Bt = Wl + (size_t)dir * DIMX * G3 + nt * BN;
                float* Ct = xgdst + (size_t)dir * MROWS * G3 +
                            ((size_t)b * TLEN + (size_t)ci * BM) * G3 + nt * BN;

                unsigned long long acc[4][4];
#pragma unroll
                for (int i = 0; i < 4; i++)
#pragma unroll
                    for (int q = 0; q < 4; q++) acc[i][q] = 0ULL;

                float4 a0r = *(const float4*)&At[(size_t)arow * DIMX + ak];
                float4 a1r = make_float4(0.f, 0.f, 0.f, 0.f);
                if (tid < 128)
                    a1r = *(const float4*)&At[(size_t)(arow + 96) * DIMX + ak];
                float4 b0r = *(const float4*)&Bt[(size_t)brow * G3 + bc];

                sh_As[0][ak + 0][arow] = a0r.x;
                sh_As[0][ak + 1][arow] = a0r.y;
                sh_As[0][ak + 2][arow] = a0r.z;
                sh_As[0][ak + 3][arow] = a0r.w;
                if (tid < 128) {
                    sh_As[0][ak + 0][arow + 96] = a1r.x;
                    sh_As[0][ak + 1][arow + 96] = a1r.y;
                    sh_As[0][ak + 2][arow + 96] = a1r.z;
                    sh_As[0][ak + 3][arow + 96] = a1r.w;
                }
                {
                    ulonglong2 bp0, bp1;
                    bp0.x = pk2(b0r.x, b0r.x); bp0.y = pk2(b0r.y, b0r.y);
                    bp1.x = pk2(b0r.z, b0r.z); bp1.y = pk2(b0r.w, b0r.w);
                    *(ulonglong2*)&sh_Bs[0][brow][bc] = bp0;
                    *(ulonglong2*)&sh_Bs[0][brow][bc + 2] = bp1;
                }
                __syncthreads();

                for (int cc = 0; cc < DIMX / BK; cc++) {
                    const int cur = cc & 1;
                    if (cc < DIMX / BK - 1) {
                        const int k0 = (cc + 1) * BK;
                        a0r = *(const float4*)&At[(size_t)arow * DIMX + k0 + ak];
                        if (tid < 128)
                            a1r = *(const float4*)&At[(size_t)(arow + 96) * DIMX + k0 + ak];
                        b0r = *(const float4*)&Bt[(size_t)(k0 + brow) * G3 + bc];
                    }
#pragma unroll
                    for (int k = 0; k < BK; k++) {
                        const float* Ak = &sh_As[cur][k][ty8];
                        ulonglong2 av0 = *(const ulonglong2*)(Ak);
                        ulonglong2 av1 = *(const ulonglong2*)(Ak + 4);
                        const unsigned long long* Bk = &sh_Bs[cur][k][tx4];
                        ulonglong2 bv0 = *(const ulonglong2*)(Bk);
                        ulonglong2 bv1 = *(const ulonglong2*)(Bk + 2);
                        acc[0][0] = fma2(av0.x, bv0.x, acc[0][0]);
                        acc[0][1] = fma2(av0.x, bv0.y, acc[0][1]);
                        acc[0][2] = fma2(av0.x, bv1.x, acc[0][2]);
                        acc[0][3] = fma2(av0.x, bv1.y, acc[0][3]);
                        acc[1][0] = fma2(av0.y, bv0.x, acc[1][0]);
                        acc[1][1] = fma2(av0.y, bv0.y, acc[1][1]);
                        acc[1][2] = fma2(av0.y, bv1.x, acc[1][2]);
                        acc[1][3] = fma2(av0.y, bv1.y, acc[1][3]);
                        acc[2][0] = fma2(av1.x, bv0.x, acc[2][0]);
                        acc[2][1] = fma2(av1.x, bv0.y, acc[2][1]);
                        acc[2][2] = fma2(av1.x, bv1.x, acc[2][2]);
                        acc[2][3] = fma2(av1.x, bv1.y, acc[2][3]);
                        acc[3][0] = fma2(av1.y, bv0.x, acc[3][0]);
                        acc[3][1] = fma2(av1.y, bv0.y, acc[3][1]);
                        acc[3][2] = fma2(av1.y, bv1.x, acc[3][2]);
                        acc[3][3] = fma2(av1.y, bv1.y, acc[3][3]);
                    }
                    if (cc < DIMX / BK - 1) {
                        const int nxt = cur ^ 1;
                        sh_As[nxt][ak + 0][arow] = a0r.x;
                        sh_As[nxt][ak + 1][arow] = a0r.y;
                        sh_As[nxt][ak + 2][arow] = a0r.z;
                        sh_As[nxt][ak + 3][arow] = a0r.w;
                        if (tid < 128) {
                            sh_As[nxt][ak + 0][arow + 96] = a1r.x;
                            sh_As[nxt][ak + 1][arow + 96] = a1r.y;
                            sh_As[nxt][ak + 2][arow + 96] = a1r.z;
                            sh_As[nxt][ak + 3][arow + 96] = a1r.w;
                        }
                        ulonglong2 bp0, bp1;
                        bp0.x = pk2(b0r.x, b0r.x); bp0.y = pk2(b0r.y, b0r.y);
                        bp1.x = pk2(b0r.z, b0r.z); bp1.y = pk2(b0r.w, b0r.w);
                        *(ulonglong2*)&sh_Bs[nxt][brow][bc] = bp0;
                        *(ulonglong2*)&sh_Bs[nxt][brow][bc + 2] = bp1;
                        __syncthreads();
                    }
                }

#pragma unroll
                for (int mp = 0; mp < 4; mp++) {
                    float l0, h0, l1, h1, l2, h2, l3, h3;
                    up2(acc[mp][0], l0, h0);
                    up2(acc[mp][1], l1, h1);
                    up2(acc[mp][2], l2, h2);
                    up2(acc[mp][3], l3, h3);
                    const int row = ty8 + 2 * mp;
                    *(float4*)&Ct[(size_t)row * G3 + tx4] =
                        make_float4(l0, l1, l2, l3);
                    *(float4*)&Ct[(size_t)(row + 1) * G3 + tx4] =
                        make_float4(h0, h1, h2, h3);
                }
                __syncthreads();
                if (tid == 0) {
                    __threadfence();
                    atomicAdd(&g_xgready[l][dir][b][ci], 1u);
                }
                __syncthreads();
            }
        }
    }
}

// ---------------------------------------------------------------------------
extern "C" void kernel_launch(void* const* d_in, const int* in_sizes, int n_in,
                              void* d_out, int out_size) {
    const float* x  = (const float*)d_in[0];
    const float* Wi = (const float*)d_in[1];
    const float* Wh = (const float*)d_in[2];
    const float* bh = (const float*)d_in[3];
    float* out = (float*)d_out;

    reset_flags<<<(NLAYER * 2 * BATCH * NCHUNK + 255) / 256, 256>>>();
    fused_birnn<<<NBLK, 384>>>(x, Wi, Wh, bh, out);
}